// round 16
// baseline (speedup 1.0000x reference)
#include <cuda_runtime.h>

#define N_NODES 20000
#define N_EDGES 240000
#define IN_DIM  20
#define SH_DIM  16
#define OUT_DIM 360     // 20 (mlp) + 20 (sender sum) + 320 (tensor product)
#define CAP     64      // bucket capacity per node (max in-degree bound)

// ---- scratch (zero-initialized at module load; g_count invariant: ==0 on
//      entry to kernel_launch, restored by k_aggr each call) ----
__device__ __align__(16) int    g_count[N_NODES];
__device__ __align__(16) float4 g_pos4[N_NODES];          // packed positions
__device__ __align__(16) float4 g_bucket4[N_NODES * CAP]; // {ux,uy,uz, row-bits}

// ============================================================================
// K0: pack pos [N,3] -> float4 (so endpoint gathers are single LDG.128)
// ============================================================================
__global__ void k_prep(const float* __restrict__ pos)
{
    const int n = blockIdx.x * blockDim.x + threadIdx.x;
    if (n >= N_NODES) return;
    g_pos4[n] = make_float4(pos[3 * n], pos[3 * n + 1], pos[3 * n + 2], 0.0f);
}

// ============================================================================
// K1: per-node MLP (output cols 0..19). Forked onto a side stream.
// ============================================================================
#define NPB         16                   // nodes per block
#define MLP_THREADS (NPB * IN_DIM)       // 320
#define MLP_GRID    (N_NODES / NPB)      // 1250

__global__ void k_mlp(const float* __restrict__ x,
                      const float* __restrict__ Wpre,  const float* __restrict__ bpre,
                      const float* __restrict__ Wpost, const float* __restrict__ bpost,
                      const float* __restrict__ Wsc,   const float* __restrict__ bsc,
                      float* __restrict__ out)
{
    __shared__ float4 sWpre4[IN_DIM * 5], sWpost4[IN_DIM * 5], sWsc4[IN_DIM * 5];
    __shared__ float  sb[40];
    __shared__ float  sx  [NPB * IN_DIM];
    __shared__ float  spre[NPB * IN_DIM];

    const int tid = threadIdx.x;

    if (tid < 100)       sWpre4 [tid]       = ((const float4*)Wpre )[tid];
    else if (tid < 200)  sWpost4[tid - 100] = ((const float4*)Wpost)[tid - 100];
    else if (tid < 300)  sWsc4  [tid - 200] = ((const float4*)Wsc  )[tid - 200];
    if (tid < IN_DIM) {
        sb[tid]      = bpre[tid];
        sb[20 + tid] = bpost[tid] + bsc[tid];
    }
    if (tid < 80)
        ((float4*)sx)[tid] = ((const float4*)x)[blockIdx.x * 80 + tid];
    __syncthreads();

    const int ln = tid / IN_DIM;
    const int i  = tid - ln * IN_DIM;

    float4 xr[5];
#pragma unroll
    for (int j = 0; j < 5; j++) xr[j] = ((const float4*)(sx + ln * IN_DIM))[j];

    float a = sb[i];
#pragma unroll
    for (int j = 0; j < 5; j++) {
        const float4 w = sWpre4[i * 5 + j];
        a = fmaf(xr[j].x, w.x, a);
        a = fmaf(xr[j].y, w.y, a);
        a = fmaf(xr[j].z, w.z, a);
        a = fmaf(xr[j].w, w.w, a);
    }
    spre[ln * IN_DIM + i] = fmaxf(a, 0.0f);
    __syncthreads();

    float b = sb[20 + i];
#pragma unroll
    for (int j = 0; j < 5; j++) {
        const float4 p  = ((const float4*)(spre + ln * IN_DIM))[j];
        const float4 w1 = sWpost4[i * 5 + j];
        const float4 w2 = sWsc4  [i * 5 + j];
        b = fmaf(p.x,     w1.x, b);
        b = fmaf(p.y,     w1.y, b);
        b = fmaf(p.z,     w1.z, b);
        b = fmaf(p.w,     w1.w, b);
        b = fmaf(xr[j].x, w2.x, b);
        b = fmaf(xr[j].y, w2.y, b);
        b = fmaf(xr[j].z, w2.z, b);
        b = fmaf(xr[j].w, w2.w, b);
    }
    out[(blockIdx.x * NPB + ln) * OUT_DIM + i] = b;
}

// ============================================================================
// K2: fused histogram + geometry + bucket scatter (slack kernel absorbs the
//     endpoint gathers and rsqrt). Per edge: 2 LDG.128 pos gathers, unit
//     vector, atomic rank, ONE scattered STG.128 {ux,uy,uz,row}.
// ============================================================================
__global__ void k_hist_scatter(const int* __restrict__ ei)
{
    const int i = blockIdx.x * blockDim.x + threadIdx.x;
    if (i >= N_EDGES / 2) return;
    const int2 r = __ldg(&((const int2*)ei)[i]);
    const int2 c = __ldg(&((const int2*)(ei + N_EDGES))[i]);

    const float4 pr0 = g_pos4[r.x];
    const float4 pc0 = g_pos4[c.x];
    const float4 pr1 = g_pos4[r.y];
    const float4 pc1 = g_pos4[c.y];

    float ax = pc0.x - pr0.x, ay = pc0.y - pr0.y, az = pc0.z - pr0.z;
    float ia = rsqrtf(fmaf(ax, ax, fmaf(ay, ay, fmaf(az, az, 1e-12f))));
    float bx = pc1.x - pr1.x, by = pc1.y - pr1.y, bz = pc1.z - pr1.z;
    float ib = rsqrtf(fmaf(bx, bx, fmaf(by, by, fmaf(bz, bz, 1e-12f))));

    const int rk0 = atomicAdd(&g_count[c.x], 1);
    const int rk1 = atomicAdd(&g_count[c.y], 1);
    g_bucket4[(c.x << 6) + rk0] = make_float4(ax * ia, ay * ia, az * ia,
                                              __int_as_float(r.x));
    g_bucket4[(c.y << 6) + rk1] = make_float4(bx * ib, by * ib, bz * ib,
                                              __int_as_float(r.y));
}

// ============================================================================
// K3: fused SH + gather-aggregate. One warp per destination node.
//     Chunks of 16 edges. Phase 1: coalesced bucket read + cooperative
//     high-MLP x-row prefetch into SMEM + lane-parallel SH into SMEM.
//     Phase 2: pure LDS+FMA serial accumulate (NO global loads in loop).
// ============================================================================
#define WPB 8    // warps per block (256 threads)
#define CHK 16   // edges per chunk

__global__ void k_aggr4(const float4* __restrict__ x4,
                        float* __restrict__ out)
{
    __shared__ __align__(16) float s_sh[WPB][CHK][20];  // sh1..sh15, pad
    __shared__ __align__(16) float s_x [WPB][CHK][20];  // staged sender rows
    __shared__ int   s_r [WPB][CHK];

    const int warp = (blockIdx.x * blockDim.x + threadIdx.x) >> 5;
    const int w    = (threadIdx.x >> 5);
    const int lane = threadIdx.x & 31;
    if (warp >= N_NODES) return;
    const int n = warp;

    const int deg = g_count[n];
    if (lane == 0) g_count[n] = 0;        // restore invariant for next replay
    const int s0 = n << 6;                // bucket base
    const int s1 = s0 + deg;

    float accS = 0.0f;
    float acc[15];
#pragma unroll
    for (int j = 0; j < 15; j++) acc[j] = 0.0f;

    for (int base = s0; base < s1; base += CHK) {
        const int m = min(CHK, s1 - base);

        // ---- phase 1a: coalesced bucket read ----
        float4 u;
        if (lane < m) {
            u = g_bucket4[base + lane];                // coalesced LDG.128
            s_r[w][lane] = __float_as_int(u.w);
        }
        __syncwarp();

        // ---- phase 1b: cooperative x prefetch (m*5 float4, MLP<=3/lane) ----
        for (int k = lane; k < m * 5; k += 32) {
            const int t = k / 5, c = k - t * 5;
            ((float4*)&s_x[w][t][0])[c] = __ldg(&x4[s_r[w][t] * 5 + c]);
        }

        // ---- phase 1c: lane-parallel SH polynomial ----
        if (lane < m) {
            const float X = u.x, Y = u.y, Z = u.z;
            const float X2 = X * X, Y2 = Y * Y, Z2 = Z * Z;
            float4* q = (float4*)&s_sh[w][lane][0];
            q[0] = make_float4(0.4886025119029199f * Y,
                               0.4886025119029199f * Z,
                               0.4886025119029199f * X,
                               1.0925484305920792f * X * Y);
            q[1] = make_float4(1.0925484305920792f * Y * Z,
                               0.31539156525252005f * (3.0f * Z2 - 1.0f),
                               1.0925484305920792f * X * Z,
                               0.5462742152960396f * (X2 - Y2));
            q[2] = make_float4(0.5900435899266435f * Y * (3.0f * X2 - Y2),
                               2.890611442640554f  * X * Y * Z,
                               0.4570457994644658f * Y * (5.0f * Z2 - 1.0f),
                               0.3731763325901154f * Z * (5.0f * Z2 - 3.0f));
            q[3] = make_float4(0.4570457994644658f * X * (5.0f * Z2 - 1.0f),
                               1.445305721320277f  * Z * (X2 - Y2),
                               0.5900435899266435f * X * (X2 - 3.0f * Y2),
                               0.0f);
        }
        __syncwarp();

        // ---- phase 2: serial accumulate, pure LDS+FMA (2x unrolled) ----
        int t = 0;
        for (; t + 2 <= m; t += 2) {
            const float sA = (lane < IN_DIM) ? s_x[w][t][lane]     : 0.0f;
            const float sB = (lane < IN_DIM) ? s_x[w][t + 1][lane] : 0.0f;
            const float4* shA = (const float4*)&s_sh[w][t][0];
            const float4* shB = (const float4*)&s_sh[w][t + 1][0];
            const float4 a0 = shA[0], a1 = shA[1], a2 = shA[2], a3 = shA[3];
            const float4 b0 = shB[0], b1 = shB[1], b2 = shB[2], b3 = shB[3];

            accS += sA + sB;
            acc[0]  = fmaf(sA, a0.x, fmaf(sB, b0.x, acc[0]));
            acc[1]  = fmaf(sA, a0.y, fmaf(sB, b0.y, acc[1]));
            acc[2]  = fmaf(sA, a0.z, fmaf(sB, b0.z, acc[2]));
            acc[3]  = fmaf(sA, a0.w, fmaf(sB, b0.w, acc[3]));
            acc[4]  = fmaf(sA, a1.x, fmaf(sB, b1.x, acc[4]));
            acc[5]  = fmaf(sA, a1.y, fmaf(sB, b1.y, acc[5]));
            acc[6]  = fmaf(sA, a1.z, fmaf(sB, b1.z, acc[6]));
            acc[7]  = fmaf(sA, a1.w, fmaf(sB, b1.w, acc[7]));
            acc[8]  = fmaf(sA, a2.x, fmaf(sB, b2.x, acc[8]));
            acc[9]  = fmaf(sA, a2.y, fmaf(sB, b2.y, acc[9]));
            acc[10] = fmaf(sA, a2.z, fmaf(sB, b2.z, acc[10]));
            acc[11] = fmaf(sA, a2.w, fmaf(sB, b2.w, acc[11]));
            acc[12] = fmaf(sA, a3.x, fmaf(sB, b3.x, acc[12]));
            acc[13] = fmaf(sA, a3.y, fmaf(sB, b3.y, acc[13]));
            acc[14] = fmaf(sA, a3.z, fmaf(sB, b3.z, acc[14]));
        }
        if (t < m) {
            const float sA = (lane < IN_DIM) ? s_x[w][t][lane] : 0.0f;
            const float4* shA = (const float4*)&s_sh[w][t][0];
            const float4 a0 = shA[0], a1 = shA[1], a2 = shA[2], a3 = shA[3];
            accS += sA;
            acc[0]  = fmaf(sA, a0.x, acc[0]);
            acc[1]  = fmaf(sA, a0.y, acc[1]);
            acc[2]  = fmaf(sA, a0.z, acc[2]);
            acc[3]  = fmaf(sA, a0.w, acc[3]);
            acc[4]  = fmaf(sA, a1.x, acc[4]);
            acc[5]  = fmaf(sA, a1.y, acc[5]);
            acc[6]  = fmaf(sA, a1.z, acc[6]);
            acc[7]  = fmaf(sA, a1.w, acc[7]);
            acc[8]  = fmaf(sA, a2.x, acc[8]);
            acc[9]  = fmaf(sA, a2.y, acc[9]);
            acc[10] = fmaf(sA, a2.z, acc[10]);
            acc[11] = fmaf(sA, a2.w, acc[11]);
            acc[12] = fmaf(sA, a3.x, acc[12]);
            acc[13] = fmaf(sA, a3.y, acc[13]);
            acc[14] = fmaf(sA, a3.z, acc[14]);
        }
        __syncwarp();
    }

    if (lane < IN_DIM) {
        float* base = out + n * OUT_DIM;
        base[20 + lane] = accS;
        float4* p = (float4*)(base + 40 + lane * SH_DIM);
        p[0] = make_float4(accS * 0.28209479177387814f, acc[0],  acc[1],  acc[2]);
        p[1] = make_float4(acc[3],  acc[4],  acc[5],  acc[6]);
        p[2] = make_float4(acc[7],  acc[8],  acc[9],  acc[10]);
        p[3] = make_float4(acc[11], acc[12], acc[13], acc[14]);
    }
}

// ============================================================================
// Launcher: stream0 = prep -> hist_scatter -> aggr4; mlp forked on side
// stream (data-independent: disjoint out columns, disjoint scratch).
// ============================================================================
extern "C" void kernel_launch(void* const* d_in, const int* in_sizes, int n_in,
                              void* d_out, int out_size)
{
    const float* x     = (const float*)d_in[0];
    const float* pos   = (const float*)d_in[1];
    const int*   ei    = (const int*)  d_in[2];
    const float* Wpre  = (const float*)d_in[3];
    const float* bpre  = (const float*)d_in[4];
    const float* Wpost = (const float*)d_in[5];
    const float* bpost = (const float*)d_in[6];
    const float* Wsc   = (const float*)d_in[7];
    const float* bsc   = (const float*)d_in[8];
    float* out = (float*)d_out;

    cudaStream_t s2;
    cudaEvent_t  eFork, eJoin;
    cudaStreamCreateWithFlags(&s2, cudaStreamNonBlocking);
    cudaEventCreateWithFlags(&eFork, cudaEventDisableTiming);
    cudaEventCreateWithFlags(&eJoin, cudaEventDisableTiming);

    cudaEventRecord(eFork, 0);
    cudaStreamWaitEvent(s2, eFork, 0);

    k_mlp<<<MLP_GRID, MLP_THREADS, 0, s2>>>(x, Wpre, bpre, Wpost, bpost,
                                            Wsc, bsc, out);
    cudaEventRecord(eJoin, s2);

    k_prep        <<<(N_NODES + 255) / 256, 256>>>(pos);
    k_hist_scatter<<<(N_EDGES / 2 + 255) / 256, 256>>>(ei);
    k_aggr4       <<<(N_NODES * 32 + 255) / 256, 256>>>((const float4*)x, out);

    cudaStreamWaitEvent(0, eJoin, 0);

    cudaEventDestroy(eFork);
    cudaEventDestroy(eJoin);
    cudaStreamDestroy(s2);
}

// round 17
// speedup vs baseline: 1.0662x; 1.0662x over previous
#include <cuda_runtime.h>

#define N_NODES 20000
#define N_EDGES 240000
#define IN_DIM  20
#define SH_DIM  16
#define OUT_DIM 360     // 20 (mlp) + 20 (sender sum) + 320 (tensor product)
#define CAP     64      // bucket capacity per node (max in-degree bound)

// ---- scratch (zero-initialized at module load; g_count invariant: ==0 on
//      entry to kernel_launch, restored by k_aggr each call) ----
__device__ __align__(16) int    g_count[N_NODES];
__device__ __align__(16) float4 g_pos4[N_NODES];          // packed positions
__device__ __align__(16) float4 g_bucket4[N_NODES * CAP]; // {ux,uy,uz, row-bits}

// ============================================================================
// K0: pack pos [N,3] -> float4
// ============================================================================
__global__ void k_prep(const float* __restrict__ pos)
{
    const int n = blockIdx.x * blockDim.x + threadIdx.x;
    if (n >= N_NODES) return;
    g_pos4[n] = make_float4(pos[3 * n], pos[3 * n + 1], pos[3 * n + 2], 0.0f);
}

// ============================================================================
// K1: per-node MLP (output cols 0..19). Forked onto a side stream.
// ============================================================================
#define NPB         16
#define MLP_THREADS (NPB * IN_DIM)       // 320
#define MLP_GRID    (N_NODES / NPB)      // 1250

__global__ void k_mlp(const float* __restrict__ x,
                      const float* __restrict__ Wpre,  const float* __restrict__ bpre,
                      const float* __restrict__ Wpost, const float* __restrict__ bpost,
                      const float* __restrict__ Wsc,   const float* __restrict__ bsc,
                      float* __restrict__ out)
{
    __shared__ float4 sWpre4[IN_DIM * 5], sWpost4[IN_DIM * 5], sWsc4[IN_DIM * 5];
    __shared__ float  sb[40];
    __shared__ float  sx  [NPB * IN_DIM];
    __shared__ float  spre[NPB * IN_DIM];

    const int tid = threadIdx.x;

    if (tid < 100)       sWpre4 [tid]       = ((const float4*)Wpre )[tid];
    else if (tid < 200)  sWpost4[tid - 100] = ((const float4*)Wpost)[tid - 100];
    else if (tid < 300)  sWsc4  [tid - 200] = ((const float4*)Wsc  )[tid - 200];
    if (tid < IN_DIM) {
        sb[tid]      = bpre[tid];
        sb[20 + tid] = bpost[tid] + bsc[tid];
    }
    if (tid < 80)
        ((float4*)sx)[tid] = ((const float4*)x)[blockIdx.x * 80 + tid];
    __syncthreads();

    const int ln = tid / IN_DIM;
    const int i  = tid - ln * IN_DIM;

    float4 xr[5];
#pragma unroll
    for (int j = 0; j < 5; j++) xr[j] = ((const float4*)(sx + ln * IN_DIM))[j];

    float a = sb[i];
#pragma unroll
    for (int j = 0; j < 5; j++) {
        const float4 w = sWpre4[i * 5 + j];
        a = fmaf(xr[j].x, w.x, a);
        a = fmaf(xr[j].y, w.y, a);
        a = fmaf(xr[j].z, w.z, a);
        a = fmaf(xr[j].w, w.w, a);
    }
    spre[ln * IN_DIM + i] = fmaxf(a, 0.0f);
    __syncthreads();

    float b = sb[20 + i];
#pragma unroll
    for (int j = 0; j < 5; j++) {
        const float4 p  = ((const float4*)(spre + ln * IN_DIM))[j];
        const float4 w1 = sWpost4[i * 5 + j];
        const float4 w2 = sWsc4  [i * 5 + j];
        b = fmaf(p.x,     w1.x, b);
        b = fmaf(p.y,     w1.y, b);
        b = fmaf(p.z,     w1.z, b);
        b = fmaf(p.w,     w1.w, b);
        b = fmaf(xr[j].x, w2.x, b);
        b = fmaf(xr[j].y, w2.y, b);
        b = fmaf(xr[j].z, w2.z, b);
        b = fmaf(xr[j].w, w2.w, b);
    }
    out[(blockIdx.x * NPB + ln) * OUT_DIM + i] = b;
}

// ============================================================================
// K2: fused histogram + geometry + bucket scatter.
// ============================================================================
__global__ void k_hist_scatter(const int* __restrict__ ei)
{
    const int i = blockIdx.x * blockDim.x + threadIdx.x;
    if (i >= N_EDGES / 2) return;
    const int2 r = __ldg(&((const int2*)ei)[i]);
    const int2 c = __ldg(&((const int2*)(ei + N_EDGES))[i]);

    const float4 pr0 = g_pos4[r.x];
    const float4 pc0 = g_pos4[c.x];
    const float4 pr1 = g_pos4[r.y];
    const float4 pc1 = g_pos4[c.y];

    float ax = pc0.x - pr0.x, ay = pc0.y - pr0.y, az = pc0.z - pr0.z;
    float ia = rsqrtf(fmaf(ax, ax, fmaf(ay, ay, fmaf(az, az, 1e-12f))));
    float bx = pc1.x - pr1.x, by = pc1.y - pr1.y, bz = pc1.z - pr1.z;
    float ib = rsqrtf(fmaf(bx, bx, fmaf(by, by, fmaf(bz, bz, 1e-12f))));

    const int rk0 = atomicAdd(&g_count[c.x], 1);
    const int rk1 = atomicAdd(&g_count[c.y], 1);
    g_bucket4[(c.x << 6) + rk0] = make_float4(ax * ia, ay * ia, az * ia,
                                              __int_as_float(r.x));
    g_bucket4[(c.y << 6) + rk1] = make_float4(bx * ib, by * ib, bz * ib,
                                              __int_as_float(r.y));
}

// ============================================================================
// K3: fused SH + gather-aggregate. One warp per node, chunks of 16 edges.
//     - row ids broadcast via shfl (no SMEM index array)
//     - whole-chunk x prefetch into REGISTERS (16 independent LDGs, MLP=16)
//     - SH rows written for ALL 16 lanes each chunk (always finite) so the
//       fully-unrolled phase 2 needs no guards: xv[t]=0 for t>=m.
// ============================================================================
#define WPB 8    // warps per block (256 threads)
#define CHK 16   // edges per chunk

__global__ void k_aggr5(const float* __restrict__ x,
                        float* __restrict__ out)
{
    __shared__ __align__(16) float s_sh[WPB][CHK][20];  // sh1..sh15, pad

    const int warp = (blockIdx.x * blockDim.x + threadIdx.x) >> 5;
    const int w    = (threadIdx.x >> 5);
    const int lane = threadIdx.x & 31;
    if (warp >= N_NODES) return;
    const int n = warp;

    const int deg = g_count[n];           // L2 load, overlaps bucket load below
    if (lane == 0) g_count[n] = 0;        // restore invariant for next replay
    const int s0 = n << 6;

    float accS = 0.0f;
    float acc[15];
#pragma unroll
    for (int j = 0; j < 15; j++) acc[j] = 0.0f;

    for (int base = s0; base < s0 + deg; base += CHK) {
        const int m = min(CHK, s0 + deg - base);

        // ---- bucket read: unguarded by m (within CAP; contents always finite)
        float4 u = make_float4(0.0f, 0.0f, 0.0f, 0.0f);
        if (lane < CHK) u = g_bucket4[base + lane];

        // ---- SH for all CHK rows (finite even for stale lanes) ----
        if (lane < CHK) {
            const float X = u.x, Y = u.y, Z = u.z;
            const float X2 = X * X, Y2 = Y * Y, Z2 = Z * Z;
            float4* q = (float4*)&s_sh[w][lane][0];
            q[0] = make_float4(0.4886025119029199f * Y,
                               0.4886025119029199f * Z,
                               0.4886025119029199f * X,
                               1.0925484305920792f * X * Y);
            q[1] = make_float4(1.0925484305920792f * Y * Z,
                               0.31539156525252005f * (3.0f * Z2 - 1.0f),
                               1.0925484305920792f * X * Z,
                               0.5462742152960396f * (X2 - Y2));
            q[2] = make_float4(0.5900435899266435f * Y * (3.0f * X2 - Y2),
                               2.890611442640554f  * X * Y * Z,
                               0.4570457994644658f * Y * (5.0f * Z2 - 1.0f),
                               0.3731763325901154f * Z * (5.0f * Z2 - 3.0f));
            q[3] = make_float4(0.4570457994644658f * X * (5.0f * Z2 - 1.0f),
                               1.445305721320277f  * Z * (X2 - Y2),
                               0.5900435899266435f * X * (X2 - 3.0f * Y2),
                               0.0f);
        }

        // ---- whole-chunk x prefetch into registers (16 independent LDGs) ----
        const int rowbits = __float_as_int(u.w);
        float xv[CHK];
#pragma unroll
        for (int t = 0; t < CHK; t++) {
            const int rt = __shfl_sync(0xffffffffu, rowbits, t);
            float v = 0.0f;
            if (lane < IN_DIM && t < m) v = __ldg(&x[rt * IN_DIM + lane]);
            xv[t] = v;
        }
        __syncwarp();

        // ---- phase 2: fully unrolled, pure registers + broadcast LDS ----
#pragma unroll
        for (int t = 0; t < CHK; t++) {
            const float sA = xv[t];
            const float4* sh = (const float4*)&s_sh[w][t][0];
            const float4 a0 = sh[0], a1 = sh[1], a2 = sh[2], a3 = sh[3];
            accS += sA;
            acc[0]  = fmaf(sA, a0.x, acc[0]);
            acc[1]  = fmaf(sA, a0.y, acc[1]);
            acc[2]  = fmaf(sA, a0.z, acc[2]);
            acc[3]  = fmaf(sA, a0.w, acc[3]);
            acc[4]  = fmaf(sA, a1.x, acc[4]);
            acc[5]  = fmaf(sA, a1.y, acc[5]);
            acc[6]  = fmaf(sA, a1.z, acc[6]);
            acc[7]  = fmaf(sA, a1.w, acc[7]);
            acc[8]  = fmaf(sA, a2.x, acc[8]);
            acc[9]  = fmaf(sA, a2.y, acc[9]);
            acc[10] = fmaf(sA, a2.z, acc[10]);
            acc[11] = fmaf(sA, a2.w, acc[11]);
            acc[12] = fmaf(sA, a3.x, acc[12]);
            acc[13] = fmaf(sA, a3.y, acc[13]);
            acc[14] = fmaf(sA, a3.z, acc[14]);
        }
        __syncwarp();
    }

    if (lane < IN_DIM) {
        float* base = out + n * OUT_DIM;
        base[20 + lane] = accS;
        float4* p = (float4*)(base + 40 + lane * SH_DIM);
        p[0] = make_float4(accS * 0.28209479177387814f, acc[0],  acc[1],  acc[2]);
        p[1] = make_float4(acc[3],  acc[4],  acc[5],  acc[6]);
        p[2] = make_float4(acc[7],  acc[8],  acc[9],  acc[10]);
        p[3] = make_float4(acc[11], acc[12], acc[13], acc[14]);
    }
}

// ============================================================================
// Launcher: stream0 = prep -> hist_scatter -> aggr5; mlp forked on side stream.
// ============================================================================
extern "C" void kernel_launch(void* const* d_in, const int* in_sizes, int n_in,
                              void* d_out, int out_size)
{
    const float* x     = (const float*)d_in[0];
    const float* pos   = (const float*)d_in[1];
    const int*   ei    = (const int*)  d_in[2];
    const float* Wpre  = (const float*)d_in[3];
    const float* bpre  = (const float*)d_in[4];
    const float* Wpost = (const float*)d_in[5];
    const float* bpost = (const float*)d_in[6];
    const float* Wsc   = (const float*)d_in[7];
    const float* bsc   = (const float*)d_in[8];
    float* out = (float*)d_out;

    cudaStream_t s2;
    cudaEvent_t  eFork, eJoin;
    cudaStreamCreateWithFlags(&s2, cudaStreamNonBlocking);
    cudaEventCreateWithFlags(&eFork, cudaEventDisableTiming);
    cudaEventCreateWithFlags(&eJoin, cudaEventDisableTiming);

    cudaEventRecord(eFork, 0);
    cudaStreamWaitEvent(s2, eFork, 0);

    k_mlp<<<MLP_GRID, MLP_THREADS, 0, s2>>>(x, Wpre, bpre, Wpost, bpost,
                                            Wsc, bsc, out);
    cudaEventRecord(eJoin, s2);

    k_prep        <<<(N_NODES + 255) / 256, 256>>>(pos);
    k_hist_scatter<<<(N_EDGES / 2 + 255) / 256, 256>>>(ei);
    k_aggr5       <<<(N_NODES * 32 + 255) / 256, 256>>>(x, out);

    cudaStreamWaitEvent(0, eJoin, 0);

    cudaEventDestroy(eFork);
    cudaEventDestroy(eJoin);
    cudaStreamDestroy(s2);
}